// round 2
// baseline (speedup 1.0000x reference)
#include <cuda_runtime.h>
#include <cstdint>

// ---------------------------------------------------------------------------
// Problem: B=512, N=256, H=128
//   hidden = emb[idx]                      [512,256,128]
//   A2 = A[:,:, :256] + A[:,:,256:]        [512,256,256]
//   d_i = rsqrt(sum_j A2[i,j] + 1)
//   A_mix[i,j] = 0.8*d_i*d_j*A2[i,j]               (i != j)
//   A_mix[i,i] = 0.1 + 0.7*d_i*d_i*(A2[i,i] + 1)
//   out = A_mix @ (A_mix @ hidden)
// ---------------------------------------------------------------------------

#define Bsz 512
#define Nn  256
#define Hh  128
#define NNODE 50000

// Scratch (static device globals; no runtime allocation)
__device__ float g_A2[(size_t)Bsz * Nn * Nn];   // 128 MiB
__device__ float g_d [(size_t)Bsz * Nn];
__device__ float g_H1[(size_t)Bsz * Nn * Hh];   // 64 MiB
__device__ int   g_idx64;                       // 1 if indices are int64

// ---------------------------------------------------------------------------
// Kernel 0: detect index dtype. True int64 indices are < 50000 -> high words
// all zero. int32 data reinterpreted as int64 puts a random index in the high
// word -> nonzero with overwhelming probability.
// ---------------------------------------------------------------------------
__global__ void detect_kernel(const unsigned long long* __restrict__ idx) {
    int is64 = 1;
    #pragma unroll
    for (int i = 0; i < 16; i++)
        if (idx[i] >> 32) is64 = 0;
    g_idx64 = is64;
}

// ---------------------------------------------------------------------------
// Kernel 1: A2 = Ain + Aout, d = rsqrt(rowsum(A2)+1)
// grid (256, 512), block 256. One block per (row, batch).
// ---------------------------------------------------------------------------
__global__ void prep_kernel(const float* __restrict__ A) {
    int i = blockIdx.x;
    int b = blockIdx.y;
    int j = threadIdx.x;

    const float* row = A + ((size_t)(b * Nn + i)) * (2 * Nn);
    float v = row[j] + row[j + Nn];
    g_A2[((size_t)(b * Nn + i)) * Nn + j] = v;

    __shared__ float red[8];
    float s = v;
    #pragma unroll
    for (int o = 16; o; o >>= 1) s += __shfl_xor_sync(0xFFFFFFFFu, s, o);
    if ((j & 31) == 0) red[j >> 5] = s;
    __syncthreads();
    if (j < 8) {
        float t = red[j];
        #pragma unroll
        for (int o = 4; o; o >>= 1) t += __shfl_xor_sync(0xFFu, t, o);
        if (j == 0) g_d[b * Nn + i] = rsqrtf(t + 1.0f);
    }
}

// ---------------------------------------------------------------------------
// TF32 helpers
// ---------------------------------------------------------------------------
__device__ __forceinline__ float to_tf32(float x) {
    uint32_t u;
    asm("cvt.rna.tf32.f32 %0, %1;" : "=r"(u) : "f"(x));
    return __uint_as_float(u);
}

__device__ __forceinline__ void mma_tf32(float* c, const uint32_t* a, const uint32_t* b) {
    asm volatile(
        "mma.sync.aligned.m16n8k8.row.col.f32.tf32.tf32.f32 "
        "{%0,%1,%2,%3}, {%4,%5,%6,%7}, {%8,%9}, {%0,%1,%2,%3};\n"
        : "+f"(c[0]), "+f"(c[1]), "+f"(c[2]), "+f"(c[3])
        : "r"(a[0]), "r"(a[1]), "r"(a[2]), "r"(a[3]),
          "r"(b[0]), "r"(b[1]));
}

// ---------------------------------------------------------------------------
// Kernel 2/3: batched GEMM  C[256,128] = A_mix[256,256] @ B[256,128]
// round == 0 : B = gather(emb, idx), C -> g_H1
// round == 1 : B = g_H1,             C -> out
// grid (2, 512). block 256 (8 warps), warp tile 64x32.
// ---------------------------------------------------------------------------
#define SA_STRIDE 36
#define SB_STRIDE 136

__global__ __launch_bounds__(256, 2)
void sgc_gemm(const void* __restrict__ idx_raw,
              const float* __restrict__ emb,
              float* __restrict__ out,
              int round) {
    __shared__ float sA[128 * SA_STRIDE];
    __shared__ float sB[32  * SB_STRIDE];
    __shared__ float sd[Nn];

    const int b    = blockIdx.y;
    const int row0 = blockIdx.x * 128;
    const int tid  = threadIdx.x;
    const int lane = tid & 31;
    const int w    = tid >> 5;
    const int wm   = w & 1;
    const int wn   = w >> 1;
    const int gr   = lane >> 2;
    const int tc   = lane & 3;

    const int idx64 = g_idx64;

    sd[tid] = g_d[b * Nn + tid];
    __syncthreads();

    float acc[4][4][4];
    #pragma unroll
    for (int mt = 0; mt < 4; mt++)
        #pragma unroll
        for (int nt = 0; nt < 4; nt++)
            #pragma unroll
            for (int e = 0; e < 4; e++) acc[mt][nt][e] = 0.0f;

    const float* __restrict__ A2b = g_A2 + (size_t)b * Nn * Nn;

    for (int kt = 0; kt < 8; ++kt) {
        const int k0 = kt * 32;

        // ---- stage A tile [128 x 32] with on-the-fly A_mix transform ----
        #pragma unroll
        for (int it = 0; it < 4; ++it) {
            int f  = tid + it * 256;
            int r  = f >> 3;
            int c4 = f & 7;
            int gi = row0 + r;
            float4 av = *(const float4*)(A2b + (size_t)gi * Nn + k0 + c4 * 4);
            float di = sd[gi];
            float vals[4] = {av.x, av.y, av.z, av.w};
            float o[4];
            #pragma unroll
            for (int e = 0; e < 4; e++) {
                int k = k0 + c4 * 4 + e;
                float v;
                if (gi == k) v = 0.1f + 0.7f * di * di * (vals[e] + 1.0f);
                else         v = 0.8f * di * sd[k] * vals[e];
                o[e] = to_tf32(v);
            }
            *(float4*)(sA + r * SA_STRIDE + c4 * 4) = make_float4(o[0], o[1], o[2], o[3]);
        }

        // ---- stage B tile [32 x 128] (gather or direct) ----
        #pragma unroll
        for (int it = 0; it < 4; ++it) {
            int f  = tid + it * 256;
            int r  = f >> 5;
            int c4 = f & 31;
            int gk = k0 + r;
            const float* src;
            if (round == 0) {
                int pos = b * Nn + gk;
                long long node;
                if (idx64) node = ((const long long*)idx_raw)[pos];
                else       node = ((const int*)idx_raw)[pos];
                if (node < 0) node = 0;
                if (node >= NNODE) node = NNODE - 1;
                src = emb + (size_t)node * Hh;
            } else {
                src = g_H1 + ((size_t)(b * Nn + gk)) * Hh;
            }
            float4 bv = *(const float4*)(src + c4 * 4);
            bv.x = to_tf32(bv.x); bv.y = to_tf32(bv.y);
            bv.z = to_tf32(bv.z); bv.w = to_tf32(bv.w);
            *(float4*)(sB + r * SB_STRIDE + c4 * 4) = bv;
        }

        __syncthreads();

        // ---- compute: 4 k8 sub-steps ----
        #pragma unroll
        for (int ks = 0; ks < 4; ++ks) {
            const int kk = ks * 8;
            uint32_t af[4][4], bf[4][2];
            #pragma unroll
            for (int mt = 0; mt < 4; mt++) {
                int rb = wm * 64 + mt * 16;
                af[mt][0] = __float_as_uint(sA[(rb + gr)     * SA_STRIDE + kk + tc]);
                af[mt][1] = __float_as_uint(sA[(rb + 8 + gr) * SA_STRIDE + kk + tc]);
                af[mt][2] = __float_as_uint(sA[(rb + gr)     * SA_STRIDE + kk + tc + 4]);
                af[mt][3] = __float_as_uint(sA[(rb + 8 + gr) * SA_STRIDE + kk + tc + 4]);
            }
            #pragma unroll
            for (int nt = 0; nt < 4; nt++) {
                int cb = wn * 32 + nt * 8;
                bf[nt][0] = __float_as_uint(sB[(kk + tc)     * SB_STRIDE + cb + gr]);
                bf[nt][1] = __float_as_uint(sB[(kk + tc + 4) * SB_STRIDE + cb + gr]);
            }
            #pragma unroll
            for (int mt = 0; mt < 4; mt++)
                #pragma unroll
                for (int nt = 0; nt < 4; nt++)
                    mma_tf32(acc[mt][nt], af[mt], bf[nt]);
        }

        __syncthreads();
    }

    // ---- epilogue ----
    float* __restrict__ dst = (round == 0) ? (g_H1 + (size_t)b * Nn * Hh)
                                           : (out  + (size_t)b * Nn * Hh);
    #pragma unroll
    for (int mt = 0; mt < 4; mt++) {
        int r_lo = row0 + wm * 64 + mt * 16 + gr;
        #pragma unroll
        for (int nt = 0; nt < 4; nt++) {
            int col = wn * 32 + nt * 8 + tc * 2;
            float2 v0 = make_float2(acc[mt][nt][0], acc[mt][nt][1]);
            float2 v1 = make_float2(acc[mt][nt][2], acc[mt][nt][3]);
            *(float2*)(dst + (size_t)r_lo       * Hh + col) = v0;
            *(float2*)(dst + (size_t)(r_lo + 8) * Hh + col) = v1;
        }
    }
}

// ---------------------------------------------------------------------------
// Launch
// ---------------------------------------------------------------------------
extern "C" void kernel_launch(void* const* d_in, const int* in_sizes, int n_in,
                              void* d_out, int out_size) {
    const void*  inputs = nullptr;   // [512,256] int32 or int64
    const float* A      = nullptr;   // [512,256,512] f32
    const float* emb    = nullptr;   // [50000,128] f32

    for (int i = 0; i < n_in; ++i) {
        if (in_sizes[i] == Bsz * Nn)               inputs = d_in[i];
        else if (in_sizes[i] == Bsz * Nn * 2 * Nn) A      = (const float*)d_in[i];
        else if (in_sizes[i] == NNODE * Hh)        emb    = (const float*)d_in[i];
    }
    if (!inputs) inputs = d_in[0];
    if (!A)      A      = (const float*)d_in[1];
    if (!emb)    emb    = (const float*)d_in[2];

    float* out = (float*)d_out;

    detect_kernel<<<1, 1>>>((const unsigned long long*)inputs);
    prep_kernel<<<dim3(Nn, Bsz), 256>>>(A);
    sgc_gemm<<<dim3(2, Bsz), 256>>>(inputs, emb, out, 0);
    sgc_gemm<<<dim3(2, Bsz), 256>>>(inputs, emb, out, 1);
}

// round 3
// speedup vs baseline: 1.2308x; 1.2308x over previous
#include <cuda_runtime.h>
#include <cstdint>

// ---------------------------------------------------------------------------
// B=512, N=256, H=128
//   A2 = A[:,:,:256] + A[:,:,256:]
//   d_i = rsqrt(rowsum(A2)+1)
//   A_mix[i,j] = 0.8*d_i*d_j*A2[i,j]  (i!=j),   0.1 + 0.7*d_i^2*(A2[i,i]+1)  (i==j)
//   out = A_mix @ (A_mix @ emb[idx])
// ---------------------------------------------------------------------------

#define Bsz 512
#define Nn  256
#define Hh  128
#define NNODE 50000

__device__ float g_A2[(size_t)Bsz * Nn * Nn];   // 128 MiB scratch
__device__ float g_d [(size_t)Bsz * Nn];
__device__ float g_H1[(size_t)Bsz * Nn * Hh];   // 64 MiB scratch
__device__ int   g_idx64;

// ---------------------------------------------------------------------------
// Kernel 0: index dtype detection (int64 indices < 50000 -> high words zero)
// ---------------------------------------------------------------------------
__global__ void detect_kernel(const unsigned long long* __restrict__ idx) {
    int is64 = 1;
    #pragma unroll
    for (int i = 0; i < 16; i++)
        if (idx[i] >> 32) is64 = 0;
    g_idx64 = is64;
}

// ---------------------------------------------------------------------------
// Kernel 1: prep. Warp per row. lane reads 2 float4 per half (MLP=4).
// grid (32, 512), block 256 (8 warps -> 8 rows/block).
// ---------------------------------------------------------------------------
__global__ __launch_bounds__(256)
void prep_kernel(const float* __restrict__ A) {
    const int lane = threadIdx.x & 31;
    const int wid  = threadIdx.x >> 5;
    const int i    = blockIdx.x * 8 + wid;   // row
    const int b    = blockIdx.y;

    const float* row = A + ((size_t)(b * Nn + i)) * (2 * Nn);
    const int j1 = lane * 4;
    const int j2 = lane * 4 + 128;

    float4 a0 = *(const float4*)(row + j1);
    float4 a1 = *(const float4*)(row + j2);
    float4 b0 = *(const float4*)(row + Nn + j1);
    float4 b1 = *(const float4*)(row + Nn + j2);

    float4 v0 = make_float4(a0.x + b0.x, a0.y + b0.y, a0.z + b0.z, a0.w + b0.w);
    float4 v1 = make_float4(a1.x + b1.x, a1.y + b1.y, a1.z + b1.z, a1.w + b1.w);

    float* dst = g_A2 + ((size_t)(b * Nn + i)) * Nn;
    *(float4*)(dst + j1) = v0;
    *(float4*)(dst + j2) = v1;

    float s = v0.x + v0.y + v0.z + v0.w + v1.x + v1.y + v1.z + v1.w;
    #pragma unroll
    for (int o = 16; o; o >>= 1) s += __shfl_xor_sync(0xFFFFFFFFu, s, o);
    if (lane == 0) g_d[b * Nn + i] = rsqrtf(s + 1.0f);
}

// ---------------------------------------------------------------------------
// TF32 helpers
// ---------------------------------------------------------------------------
__device__ __forceinline__ float to_tf32(float x) {
    uint32_t u;
    asm("cvt.rna.tf32.f32 %0, %1;" : "=r"(u) : "f"(x));
    return __uint_as_float(u);
}

__device__ __forceinline__ void mma_tf32(float* c, const uint32_t* a, const uint32_t* b) {
    asm volatile(
        "mma.sync.aligned.m16n8k8.row.col.f32.tf32.tf32.f32 "
        "{%0,%1,%2,%3}, {%4,%5,%6,%7}, {%8,%9}, {%0,%1,%2,%3};\n"
        : "+f"(c[0]), "+f"(c[1]), "+f"(c[2]), "+f"(c[3])
        : "r"(a[0]), "r"(a[1]), "r"(a[2]), "r"(a[3]),
          "r"(b[0]), "r"(b[1]));
}

__device__ __forceinline__ void cp_async16(uint32_t smem_addr, const void* gptr) {
    asm volatile("cp.async.cg.shared.global [%0], [%1], 16;\n"
                 :: "r"(smem_addr), "l"(gptr));
}
__device__ __forceinline__ void cp_commit() {
    asm volatile("cp.async.commit_group;\n");
}
__device__ __forceinline__ void cp_wait_all() {
    asm volatile("cp.async.wait_group 0;\n" ::: "memory");
}

// ---------------------------------------------------------------------------
// Kernel 2/3: batched GEMM  C[256,128] = A_mix[256,256] @ B[256,128]
// Double-buffered, software pipelined:
//   A: LDG->regs (transform + cvt.rna + STS), B: cp.async (HW tf32 truncation).
// grid (2, 512), block 256 (8 warps, warp tile 64x32).
// ---------------------------------------------------------------------------
#define SA_STRIDE 36
#define SB_STRIDE 136
#define A_BUF (128 * SA_STRIDE)   // 4608 floats
#define B_BUF (32  * SB_STRIDE)   // 4352 floats
#define SMEM_FLOATS (2 * A_BUF + 2 * B_BUF + Nn)

__global__ __launch_bounds__(256, 2)
void sgc_gemm(const void* __restrict__ idx_raw,
              const float* __restrict__ emb,
              float* __restrict__ out,
              int round) {
    extern __shared__ float smem[];
    float* sA[2] = { smem, smem + A_BUF };
    float* sB[2] = { smem + 2 * A_BUF, smem + 2 * A_BUF + B_BUF };
    float* sd    = smem + 2 * A_BUF + 2 * B_BUF;

    const int b    = blockIdx.y;
    const int row0 = blockIdx.x * 128;
    const int tid  = threadIdx.x;
    const int lane = tid & 31;
    const int w    = tid >> 5;
    const int wm   = w & 1;
    const int wn   = w >> 1;
    const int gr   = lane >> 2;
    const int tc   = lane & 3;

    const int idx64 = g_idx64;

    sd[tid] = g_d[b * Nn + tid];
    __syncthreads();

    float acc[4][4][4];
    #pragma unroll
    for (int mt = 0; mt < 4; mt++)
        #pragma unroll
        for (int nt = 0; nt < 4; nt++)
            #pragma unroll
            for (int e = 0; e < 4; e++) acc[mt][nt][e] = 0.0f;

    const float* __restrict__ A2b = g_A2 + (size_t)b * Nn * Nn;

    // per-thread staging geometry
    const int ar  = tid >> 3;          // A: rows tid/8, +32 per it (4 its)
    const int ac4 = tid & 7;           //    float4 col
    const int br  = tid >> 5;          // B: rows tid/32, +8 per it
    const int bc4 = tid & 31;

    // B source row pointer resolver
    auto b_src = [&](int gk) -> const float* {
        if (round == 0) {
            int pos = b * Nn + gk;
            long long node;
            if (idx64) node = ((const long long*)idx_raw)[pos];
            else       node = ((const int*)idx_raw)[pos];
            if (node < 0) node = 0;
            if (node >= NNODE) node = NNODE - 1;
            return emb + (size_t)node * Hh;
        }
        return g_H1 + ((size_t)(b * Nn + gk)) * Hh;
    };

    float4 ra[4];

    // ---- A reg load for k-tile kt ----
    auto load_A = [&](int kt) {
        const int k0 = kt * 32;
        #pragma unroll
        for (int it = 0; it < 4; it++) {
            int r = ar + it * 32;
            ra[it] = *(const float4*)(A2b + (size_t)(row0 + r) * Nn + k0 + ac4 * 4);
        }
    };
    // ---- A transform + STS into buffer ----
    auto store_A = [&](int kt, float* dstA) {
        const int k0 = kt * 32;
        #pragma unroll
        for (int it = 0; it < 4; it++) {
            int r  = ar + it * 32;
            int gi = row0 + r;
            float di = sd[gi];
            float vals[4] = { ra[it].x, ra[it].y, ra[it].z, ra[it].w };
            float o[4];
            #pragma unroll
            for (int e = 0; e < 4; e++) {
                int k = k0 + ac4 * 4 + e;
                float v;
                if (gi == k) v = 0.1f + 0.7f * di * di * (vals[e] + 1.0f);
                else         v = 0.8f * di * sd[k] * vals[e];
                o[e] = to_tf32(v);
            }
            *(float4*)(dstA + r * SA_STRIDE + ac4 * 4) =
                make_float4(o[0], o[1], o[2], o[3]);
        }
    };
    // ---- B cp.async into buffer ----
    auto load_B = [&](int kt, float* dstB) {
        const int k0 = kt * 32;
        uint32_t base = (uint32_t)__cvta_generic_to_shared(dstB);
        #pragma unroll
        for (int it = 0; it < 4; it++) {
            int r  = br + it * 8;
            const float* src = b_src(k0 + r) + bc4 * 4;
            cp_async16(base + (r * SB_STRIDE + bc4 * 4) * 4, src);
        }
        cp_commit();
    };
    // ---- MMA compute on a buffer pair ----
    auto compute = [&](const float* bufA, const float* bufB) {
        #pragma unroll
        for (int ks = 0; ks < 4; ++ks) {
            const int kk = ks * 8;
            uint32_t af[4][4], bf[4][2];
            #pragma unroll
            for (int mt = 0; mt < 4; mt++) {
                int rb = wm * 64 + mt * 16;
                af[mt][0] = __float_as_uint(bufA[(rb + gr)     * SA_STRIDE + kk + tc]);
                af[mt][1] = __float_as_uint(bufA[(rb + 8 + gr) * SA_STRIDE + kk + tc]);
                af[mt][2] = __float_as_uint(bufA[(rb + gr)     * SA_STRIDE + kk + tc + 4]);
                af[mt][3] = __float_as_uint(bufA[(rb + 8 + gr) * SA_STRIDE + kk + tc + 4]);
            }
            #pragma unroll
            for (int nt = 0; nt < 4; nt++) {
                int cb = wn * 32 + nt * 8;
                bf[nt][0] = __float_as_uint(bufB[(kk + tc)     * SB_STRIDE + cb + gr]);
                bf[nt][1] = __float_as_uint(bufB[(kk + tc + 4) * SB_STRIDE + cb + gr]);
            }
            #pragma unroll
            for (int mt = 0; mt < 4; mt++)
                #pragma unroll
                for (int nt = 0; nt < 4; nt++)
                    mma_tf32(acc[mt][nt], af[mt], bf[nt]);
        }
    };

    // ---- prologue: stage k-tile 0 into buffer 0 ----
    load_A(0);
    load_B(0, sB[0]);
    store_A(0, sA[0]);
    cp_wait_all();
    __syncthreads();

    // ---- main pipelined loop ----
    for (int kt = 0; kt < 8; ++kt) {
        const int cur = kt & 1;
        const int nxt = cur ^ 1;
        if (kt < 7) {
            load_A(kt + 1);          // LDGs in flight during MMAs
            load_B(kt + 1, sB[nxt]); // cp.async in flight during MMAs
        }
        compute(sA[cur], sB[cur]);
        if (kt < 7) {
            store_A(kt + 1, sA[nxt]);
            cp_wait_all();
            __syncthreads();
        }
    }

    // ---- epilogue ----
    float* __restrict__ dst = (round == 0) ? (g_H1 + (size_t)b * Nn * Hh)
                                           : (out  + (size_t)b * Nn * Hh);
    #pragma unroll
    for (int mt = 0; mt < 4; mt++) {
        int r_lo = row0 + wm * 64 + mt * 16 + gr;
        #pragma unroll
        for (int nt = 0; nt < 4; nt++) {
            int col = wn * 32 + nt * 8 + tc * 2;
            *(float2*)(dst + (size_t)r_lo       * Hh + col) =
                make_float2(acc[mt][nt][0], acc[mt][nt][1]);
            *(float2*)(dst + (size_t)(r_lo + 8) * Hh + col) =
                make_float2(acc[mt][nt][2], acc[mt][nt][3]);
        }
    }
}

// ---------------------------------------------------------------------------
// Launch
// ---------------------------------------------------------------------------
extern "C" void kernel_launch(void* const* d_in, const int* in_sizes, int n_in,
                              void* d_out, int out_size) {
    const void*  inputs = nullptr;
    const float* A      = nullptr;
    const float* emb    = nullptr;

    for (int i = 0; i < n_in; ++i) {
        if (in_sizes[i] == Bsz * Nn)               inputs = d_in[i];
        else if (in_sizes[i] == Bsz * Nn * 2 * Nn) A      = (const float*)d_in[i];
        else if (in_sizes[i] == NNODE * Hh)        emb    = (const float*)d_in[i];
    }
    if (!inputs) inputs = d_in[0];
    if (!A)      A      = (const float*)d_in[1];
    if (!emb)    emb    = (const float*)d_in[2];

    float* out = (float*)d_out;

    static bool attr_set = false;
    const int smem_bytes = SMEM_FLOATS * sizeof(float);
    if (!attr_set) {
        cudaFuncSetAttribute(sgc_gemm, cudaFuncAttributeMaxDynamicSharedMemorySize,
                             smem_bytes);
        attr_set = true;
    }

    detect_kernel<<<1, 1>>>((const unsigned long long*)inputs);
    prep_kernel<<<dim3(Nn / 8, Bsz), 256>>>(A);
    sgc_gemm<<<dim3(2, Bsz), 256, smem_bytes>>>(inputs, emb, out, 0);
    sgc_gemm<<<dim3(2, Bsz), 256, smem_bytes>>>(inputs, emb, out, 1);
}